// round 6
// baseline (speedup 1.0000x reference)
#include <cuda_runtime.h>
#include <cuda_fp16.h>
#include <cstdint>

// ---------------------------------------------------------------------------
// Shapes: inputs[16384,512] f32, adj[16384,16384] f32, W[512,128] f32
//   X   = inputs @ W   (2.1 GF)     out = adj @ X   (68.7 GF)
// Engine: mma.sync.aligned.m16n8k16.row.col.f32.f16.f16.f32.
// R6: BM=64, 128-thread CTAs (4 warps, 2x2), grid=256 -> all 148 SMs used,
// ~2 CTAs/SM for cross-CTA latency hiding (R5 was 1 CTA/SM, tensor util 62%).
// adj converted f32->fp16 inline in producer (LDG->cvt->STS), reg-buffered.
// ---------------------------------------------------------------------------

#define M_DIM 16384
#define N_DIM 128
#define K1    512

__device__ __align__(16) __half g_inH[(long)M_DIM * K1];   // inputs fp16 (16 MB)
__device__ __align__(16) __half g_WtH[N_DIM * K1];         // W^T fp16 [n][k]
__device__ __align__(16) __half g_XtH[(long)N_DIM * M_DIM];// X^T fp16 [n][m] (4 MB)

#define BM 64
#define BK 32
#define STAGES 3
#define ROW_B 80                                  // 64 B data + 16 B pad
#define A_TILE_B (BM * ROW_B)                     // 5120 B
#define B_TILE_B (128 * ROW_B)                    // 10240 B
#define SMEM_BYTES (STAGES * (A_TILE_B + B_TILE_B))  // 46080 B

// ---------------- helpers ----------------
__device__ __forceinline__ uint32_t smem_u32(const void* p) {
    uint32_t a;
    asm("{ .reg .u64 t; cvta.to.shared.u64 t, %1; cvt.u32.u64 %0, t; }"
        : "=r"(a) : "l"(p));
    return a;
}
#define CP_ASYNC16(dst, src) \
    asm volatile("cp.async.cg.shared.global [%0], [%1], 16;" :: "r"(dst), "l"(src) : "memory")
#define CP_COMMIT()  asm volatile("cp.async.commit_group;" ::: "memory")
#define CP_WAIT1()   asm volatile("cp.async.wait_group 1;" ::: "memory")
#define CP_WAIT0()   asm volatile("cp.async.wait_group 0;" ::: "memory")

__device__ __forceinline__ void mma_f16(float c[4], const uint32_t a[4], const uint32_t b[2]) {
    asm volatile(
        "mma.sync.aligned.m16n8k16.row.col.f32.f16.f16.f32 "
        "{%0,%1,%2,%3}, {%4,%5,%6,%7}, {%8,%9}, {%0,%1,%2,%3};"
        : "+f"(c[0]), "+f"(c[1]), "+f"(c[2]), "+f"(c[3])
        : "r"(a[0]), "r"(a[1]), "r"(a[2]), "r"(a[3]), "r"(b[0]), "r"(b[1]));
}
__device__ __forceinline__ void ldsm4(uint32_t r[4], uint32_t addr) {
    asm volatile("ldmatrix.sync.aligned.m8n8.x4.shared.b16 {%0,%1,%2,%3}, [%4];"
                 : "=r"(r[0]), "=r"(r[1]), "=r"(r[2]), "=r"(r[3]) : "r"(addr));
}
__device__ __forceinline__ uint32_t pack_h2(float x, float y) {
    __half2 h = __float22half2_rn(make_float2(x, y));
    return *(uint32_t*)&h;
}

// ---------------- producers ----------------
// B tile: 128 rows x 32 halves (64 B) -> 512 cp.async over 128 threads.
__device__ __forceinline__ void load_B_tile(
    uint32_t ts, const __half* __restrict__ T, long ldt, int k0, int tid)
{
    #pragma unroll
    for (int j = 0; j < 4; j++) {
        int idx = tid + j * 128;               // 0..511
        int row = idx >> 2, c = idx & 3;
        CP_ASYNC16(ts + (uint32_t)(row * ROW_B + c * 16),
                   T + (long)row * ldt + k0 + c * 8);
    }
}
// A fp16 tile (gemm1): 64 rows x 4 chunks = 256 cp.async over 128 threads.
__device__ __forceinline__ void load_A16_tile(
    uint32_t ts, const __half* __restrict__ T, long ldt, int k0, int tid)
{
    #pragma unroll
    for (int j = 0; j < 2; j++) {
        int idx = tid + j * 128;               // 0..255
        int row = idx >> 2, c = idx & 3;
        CP_ASYNC16(ts + (uint32_t)(row * ROW_B + c * 16),
                   T + (long)row * ldt + k0 + c * 8);
    }
}
// f32 A tile (adj) -> registers: 64 rows x 32 f32, 16 f32/thread.
__device__ __forceinline__ void ldg_A(float4 rb[4], const float* __restrict__ A,
                                      long lda, int k0, int tid)
{
    const float* p = A + (long)(tid >> 1) * lda + k0 + (tid & 1) * 16;
    rb[0] = *(const float4*)(p + 0);
    rb[1] = *(const float4*)(p + 4);
    rb[2] = *(const float4*)(p + 8);
    rb[3] = *(const float4*)(p + 12);
}
__device__ __forceinline__ void sts_A_cvt(uint32_t as, const float4 rb[4], int tid)
{
    uint32_t off = as + (uint32_t)((tid >> 1) * ROW_B + (tid & 1) * 32);
    uint32_t p0 = pack_h2(rb[0].x, rb[0].y), p1 = pack_h2(rb[0].z, rb[0].w);
    uint32_t p2 = pack_h2(rb[1].x, rb[1].y), p3 = pack_h2(rb[1].z, rb[1].w);
    uint32_t p4 = pack_h2(rb[2].x, rb[2].y), p5 = pack_h2(rb[2].z, rb[2].w);
    uint32_t p6 = pack_h2(rb[3].x, rb[3].y), p7 = pack_h2(rb[3].z, rb[3].w);
    asm volatile("st.shared.v4.b32 [%0], {%1,%2,%3,%4};"
                 :: "r"(off), "r"(p0), "r"(p1), "r"(p2), "r"(p3) : "memory");
    asm volatile("st.shared.v4.b32 [%0], {%1,%2,%3,%4};"
                 :: "r"(off + 16), "r"(p4), "r"(p5), "r"(p6), "r"(p7) : "memory");
}

// ---------------- compute: one BK=32 stage, warp tile 32x64 ----------------
__device__ __forceinline__ void compute_stage(uint32_t aA, uint32_t aB, float acc[2][8][4])
{
    #pragma unroll
    for (int kk = 0; kk < 2; kk++) {
        uint32_t a[2][4], b[4][4];
        #pragma unroll
        for (int mt = 0; mt < 2; mt++) ldsm4(a[mt], aA + mt * (16 * ROW_B) + kk * 32);
        #pragma unroll
        for (int p = 0; p < 4; p++)    ldsm4(b[p], aB + p * (16 * ROW_B) + kk * 32);
        #pragma unroll
        for (int mt = 0; mt < 2; mt++)
            #pragma unroll
            for (int nt = 0; nt < 8; nt++)
                mma_f16(acc[mt][nt], a[mt], &b[nt >> 1][(nt & 1) * 2]);
    }
}

// ---------------- main loop ----------------
template <int NITER, bool CONV>
__device__ __forceinline__ void gemm_mainloop(
    const void* __restrict__ Av, long lda,
    const __half* __restrict__ B, long ldb,
    float acc[2][8][4], char* smem)
{
    const int tid = threadIdx.x;
    const int wid = tid >> 5, lid = tid & 31;
    const int wr = wid >> 1, wc = wid & 1;
    const uint32_t sbase = smem_u32(smem);
    const uint32_t bregion = sbase + STAGES * A_TILE_B;

    const uint32_t Abase = (uint32_t)((wr * 32 + (lid & 15)) * ROW_B + ((lid >> 4) & 1) * 16);
    const uint32_t Bbase = (uint32_t)((wc * 64 + ((lid >> 4) & 1) * 8 + (lid & 7)) * ROW_B
                                      + ((lid >> 3) & 1) * 16);

    #pragma unroll
    for (int mt = 0; mt < 2; mt++)
        #pragma unroll
        for (int nt = 0; nt < 8; nt++)
            #pragma unroll
            for (int r = 0; r < 4; r++) acc[mt][nt][r] = 0.0f;

    const float*  Af = (const float*)Av;
    const __half* Ah = (const __half*)Av;
    float4 rb[4];

    if (CONV) ldg_A(rb, Af, lda, 0, tid);
    else      load_A16_tile(sbase, Ah, lda, 0, tid);
    load_B_tile(bregion, B, ldb, 0, tid);
    CP_COMMIT();
    if (CONV) { sts_A_cvt(sbase, rb, tid); ldg_A(rb, Af, lda, BK, tid); }
    else      load_A16_tile(sbase + A_TILE_B, Ah, lda, BK, tid);
    load_B_tile(bregion + B_TILE_B, B, ldb, BK, tid);
    CP_COMMIT();
    CP_WAIT1();
    __syncthreads();

    #pragma unroll 1
    for (int i = 0; i < NITER; i++) {
        if (CONV && (i + 1 < NITER))
            sts_A_cvt(sbase + ((i + 1) % STAGES) * A_TILE_B, rb, tid);
        if (i + 2 < NITER) {
            int s = (i + 2) % STAGES;
            if (CONV) ldg_A(rb, Af, lda, (i + 2) * BK, tid);
            else      load_A16_tile(sbase + s * A_TILE_B, Ah, lda, (i + 2) * BK, tid);
            load_B_tile(bregion + s * B_TILE_B, B, ldb, (i + 2) * BK, tid);
            CP_COMMIT();
        }
        int s = i % STAGES;
        compute_stage(sbase + s * A_TILE_B + Abase,
                      bregion + s * B_TILE_B + Bbase, acc);
        if (i + 2 < NITER) { CP_WAIT1(); } else { CP_WAIT0(); }
        __syncthreads();
    }
}

// ---------------- prepasses ----------------
__global__ __launch_bounds__(256) void cvt_inputs_kernel(const float* __restrict__ in) {
    const long n4 = (long)M_DIM * K1 / 4;
    for (long i = blockIdx.x * blockDim.x + threadIdx.x; i < n4;
         i += (long)gridDim.x * blockDim.x) {
        float4 v = ((const float4*)in)[i];
        uint2 o;
        o.x = pack_h2(v.x, v.y);
        o.y = pack_h2(v.z, v.w);
        ((uint2*)g_inH)[i] = o;
    }
}
__global__ __launch_bounds__(256) void wt_kernel(const float* __restrict__ w) {
    int i = blockIdx.x * blockDim.x + threadIdx.x;
    if (i < N_DIM * K1) {
        int n = i / K1, k = i % K1;
        g_WtH[i] = __float2half_rn(w[(long)k * N_DIM + n]);
    }
}

// ---------------- GEMM1: XtH = (inputs @ W)^T fp16 ----------------
__global__ __launch_bounds__(128, 3) void gemm1_kernel() {
    extern __shared__ char smem[];
    float acc[2][8][4];
    const int m0 = blockIdx.x * BM;

    gemm_mainloop<K1 / BK, false>(g_inH + (long)m0 * K1, K1, g_WtH, K1, acc, smem);

    const int wid = threadIdx.x >> 5, lid = threadIdx.x & 31;
    const int wr = wid >> 1, wc = wid & 1, gID = lid >> 2, tig = lid & 3;
    #pragma unroll
    for (int mt = 0; mt < 2; mt++)
        #pragma unroll
        for (int nt = 0; nt < 8; nt++) {
            int r = m0 + wr * 32 + mt * 16 + gID;
            int c = wc * 64 + nt * 8 + tig * 2;
            g_XtH[(long)c * M_DIM + r]           = __float2half_rn(acc[mt][nt][0]);
            g_XtH[(long)(c + 1) * M_DIM + r]     = __float2half_rn(acc[mt][nt][1]);
            g_XtH[(long)c * M_DIM + r + 8]       = __float2half_rn(acc[mt][nt][2]);
            g_XtH[(long)(c + 1) * M_DIM + r + 8] = __float2half_rn(acc[mt][nt][3]);
        }
}

// ---------------- GEMM2: out = adj @ X ----------------
__global__ __launch_bounds__(128, 3) void gemm2_kernel(const float* __restrict__ adj,
                                                       float* __restrict__ out) {
    extern __shared__ char smem[];
    float acc[2][8][4];
    const int m0 = blockIdx.x * BM;

    gemm_mainloop<M_DIM / BK, true>(adj + (long)m0 * M_DIM, M_DIM, g_XtH, M_DIM, acc, smem);

    const int wid = threadIdx.x >> 5, lid = threadIdx.x & 31;
    const int wr = wid >> 1, wc = wid & 1, gID = lid >> 2, tig = lid & 3;
    #pragma unroll
    for (int mt = 0; mt < 2; mt++)
        #pragma unroll
        for (int nt = 0; nt < 8; nt++) {
            long r = m0 + wr * 32 + mt * 16 + gID;
            int  c = wc * 64 + nt * 8 + tig * 2;
            *(float2*)&out[r * N_DIM + c]       = make_float2(acc[mt][nt][0], acc[mt][nt][1]);
            *(float2*)&out[(r + 8) * N_DIM + c] = make_float2(acc[mt][nt][2], acc[mt][nt][3]);
        }
}

// ---------------- launch ----------------
extern "C" void kernel_launch(void* const* d_in, const int* in_sizes, int n_in,
                              void* d_out, int out_size)
{
    const float* inputs  = (const float*)d_in[0];
    const float* adj     = (const float*)d_in[1];
    const float* weights = (const float*)d_in[2];
    float* out = (float*)d_out;

    cudaFuncSetAttribute(gemm1_kernel, cudaFuncAttributeMaxDynamicSharedMemorySize, SMEM_BYTES);
    cudaFuncSetAttribute(gemm2_kernel, cudaFuncAttributeMaxDynamicSharedMemorySize, SMEM_BYTES);

    cvt_inputs_kernel<<<1024, 256>>>(inputs);
    wt_kernel<<<(N_DIM * K1 + 255) / 256, 256>>>(weights);
    gemm1_kernel<<<M_DIM / BM, 128, SMEM_BYTES>>>();
    gemm2_kernel<<<M_DIM / BM, 128, SMEM_BYTES>>>(adj, out);
}

// round 7
// speedup vs baseline: 1.0936x; 1.0936x over previous
#include <cuda_runtime.h>
#include <cuda_fp16.h>
#include <cstdint>

// ---------------------------------------------------------------------------
// Shapes: inputs[16384,512] f32, adj[16384,16384] f32, W[512,128] f32
//   X   = inputs @ W   (2.1 GF)     out = adj @ X   (68.7 GF)
// Engine: mma.sync.aligned.m16n8k16.row.col.f32.f16.f16.f32.
// R7: back to BM=128/256thr/grid=128 (R6 breadth-first placement pathology),
// BK 32->64: half the barriers/waits, 64-MMA unbroken chains per warp per
// iter.  adj converted f32->fp16 inline (LDG->cvt->STS), reg-buffered 1 iter.
// ---------------------------------------------------------------------------

#define M_DIM 16384
#define N_DIM 128
#define K1    512

__device__ __align__(16) __half g_inH[(long)M_DIM * K1];   // inputs fp16 (16 MB)
__device__ __align__(16) __half g_WtH[N_DIM * K1];         // W^T fp16 [n][k]
__device__ __align__(16) __half g_XtH[(long)N_DIM * M_DIM];// X^T fp16 [n][m] (4 MB)

#define BK 64
#define STAGES 3
#define ROW_B 144                                 // 128 B data + 16 B pad
#define TILE_B (128 * ROW_B)                      // 18432 B per tile
#define SMEM_BYTES (STAGES * 2 * TILE_B)          // 110592 B

// ---------------- helpers ----------------
__device__ __forceinline__ uint32_t smem_u32(const void* p) {
    uint32_t a;
    asm("{ .reg .u64 t; cvta.to.shared.u64 t, %1; cvt.u32.u64 %0, t; }"
        : "=r"(a) : "l"(p));
    return a;
}
#define CP_ASYNC16(dst, src) \
    asm volatile("cp.async.cg.shared.global [%0], [%1], 16;" :: "r"(dst), "l"(src) : "memory")
#define CP_COMMIT()  asm volatile("cp.async.commit_group;" ::: "memory")
#define CP_WAIT1()   asm volatile("cp.async.wait_group 1;" ::: "memory")
#define CP_WAIT0()   asm volatile("cp.async.wait_group 0;" ::: "memory")

__device__ __forceinline__ void mma_f16(float c[4], const uint32_t a[4], const uint32_t b[2]) {
    asm volatile(
        "mma.sync.aligned.m16n8k16.row.col.f32.f16.f16.f32 "
        "{%0,%1,%2,%3}, {%4,%5,%6,%7}, {%8,%9}, {%0,%1,%2,%3};"
        : "+f"(c[0]), "+f"(c[1]), "+f"(c[2]), "+f"(c[3])
        : "r"(a[0]), "r"(a[1]), "r"(a[2]), "r"(a[3]), "r"(b[0]), "r"(b[1]));
}
__device__ __forceinline__ void ldsm4(uint32_t r[4], uint32_t addr) {
    asm volatile("ldmatrix.sync.aligned.m8n8.x4.shared.b16 {%0,%1,%2,%3}, [%4];"
                 : "=r"(r[0]), "=r"(r[1]), "=r"(r[2]), "=r"(r[3]) : "r"(addr));
}
__device__ __forceinline__ uint32_t pack_h2(float x, float y) {
    __half2 h = __float22half2_rn(make_float2(x, y));
    return *(uint32_t*)&h;
}

// ---------------- producers ----------------
// fp16 tile: 128 rows x 64 halves (128 B) -> 1024 cp.async over 256 threads.
__device__ __forceinline__ void load_f16_tile(
    uint32_t ts, const __half* __restrict__ T, long ldt, int k0, int tid)
{
    #pragma unroll
    for (int j = 0; j < 4; j++) {
        int idx = tid + j * 256;               // 0..1023
        int row = idx >> 3, c = idx & 7;
        CP_ASYNC16(ts + (uint32_t)(row * ROW_B + c * 16),
                   T + (long)row * ldt + k0 + c * 8);
    }
}
// f32 A tile (adj) -> registers: 128 rows x 64 f32, 32 f32/thread (contiguous 128B)
__device__ __forceinline__ void ldg_A(float4 rb[8], const float* __restrict__ A,
                                      long lda, int k0, int tid)
{
    const float* p = A + (long)(tid >> 1) * lda + k0 + (tid & 1) * 32;
    #pragma unroll
    for (int q = 0; q < 8; q++) rb[q] = *(const float4*)(p + q * 4);
}
// convert + STS 32 halves (64 B) at row*144 + half*64
__device__ __forceinline__ void sts_A_cvt(uint32_t as, const float4 rb[8], int tid)
{
    uint32_t off = as + (uint32_t)((tid >> 1) * ROW_B + (tid & 1) * 64);
    #pragma unroll
    for (int q = 0; q < 2; q++) {
        uint32_t p0 = pack_h2(rb[4*q+0].x, rb[4*q+0].y), p1 = pack_h2(rb[4*q+0].z, rb[4*q+0].w);
        uint32_t p2 = pack_h2(rb[4*q+1].x, rb[4*q+1].y), p3 = pack_h2(rb[4*q+1].z, rb[4*q+1].w);
        uint32_t p4 = pack_h2(rb[4*q+2].x, rb[4*q+2].y), p5 = pack_h2(rb[4*q+2].z, rb[4*q+2].w);
        uint32_t p6 = pack_h2(rb[4*q+3].x, rb[4*q+3].y), p7 = pack_h2(rb[4*q+3].z, rb[4*q+3].w);
        asm volatile("st.shared.v4.b32 [%0], {%1,%2,%3,%4};"
                     :: "r"(off + q*32), "r"(p0), "r"(p1), "r"(p2), "r"(p3) : "memory");
        asm volatile("st.shared.v4.b32 [%0], {%1,%2,%3,%4};"
                     :: "r"(off + q*32 + 16), "r"(p4), "r"(p5), "r"(p6), "r"(p7) : "memory");
    }
}

// ---------------- compute: one BK=64 stage, warp tile 64x32 ----------------
__device__ __forceinline__ void compute_stage(uint32_t aA, uint32_t aB, float acc[4][4][4])
{
    #pragma unroll
    for (int kk = 0; kk < 4; kk++) {
        uint32_t a[4][4], b[2][4];
        #pragma unroll
        for (int mt = 0; mt < 4; mt++) ldsm4(a[mt], aA + mt * (16 * ROW_B) + kk * 32);
        #pragma unroll
        for (int p = 0; p < 2; p++)   ldsm4(b[p], aB + p * (16 * ROW_B) + kk * 32);
        #pragma unroll
        for (int mt = 0; mt < 4; mt++)
            #pragma unroll
            for (int nt = 0; nt < 4; nt++)
                mma_f16(acc[mt][nt], a[mt], &b[nt >> 1][(nt & 1) * 2]);
    }
}

// ---------------- main loop ----------------
template <int NITER, bool CONV>
__device__ __forceinline__ void gemm_mainloop(
    const void* __restrict__ Av, long lda,
    const __half* __restrict__ B, long ldb,
    float acc[4][4][4], char* smem)
{
    const int tid = threadIdx.x;
    const int wid = tid >> 5, lid = tid & 31;
    const int wr = wid >> 2, wc = wid & 3;
    const uint32_t sbase = smem_u32(smem);
    const uint32_t bregion = sbase + STAGES * TILE_B;

    const uint32_t Abase = (uint32_t)((wr * 64 + (lid & 15)) * ROW_B + ((lid >> 4) & 1) * 16);
    const uint32_t Bbase = (uint32_t)((wc * 32 + ((lid >> 4) & 1) * 8 + (lid & 7)) * ROW_B
                                      + ((lid >> 3) & 1) * 16);

    #pragma unroll
    for (int mt = 0; mt < 4; mt++)
        #pragma unroll
        for (int nt = 0; nt < 4; nt++)
            #pragma unroll
            for (int r = 0; r < 4; r++) acc[mt][nt][r] = 0.0f;

    const float*  Af = (const float*)Av;
    const __half* Ah = (const __half*)Av;
    float4 rb[8];

    if (CONV) ldg_A(rb, Af, lda, 0, tid);
    else      load_f16_tile(sbase, Ah, lda, 0, tid);
    load_f16_tile(bregion, B, ldb, 0, tid);
    CP_COMMIT();
    if (CONV) { sts_A_cvt(sbase, rb, tid); ldg_A(rb, Af, lda, BK, tid); }
    else      load_f16_tile(sbase + TILE_B, Ah, lda, BK, tid);
    load_f16_tile(bregion + TILE_B, B, ldb, BK, tid);
    CP_COMMIT();
    CP_WAIT1();
    __syncthreads();

    #pragma unroll 1
    for (int i = 0; i < NITER; i++) {
        if (CONV && (i + 1 < NITER))
            sts_A_cvt(sbase + ((i + 1) % STAGES) * TILE_B, rb, tid);
        if (i + 2 < NITER) {
            int s = (i + 2) % STAGES;
            if (CONV) ldg_A(rb, Af, lda, (i + 2) * BK, tid);
            else      load_f16_tile(sbase + s * TILE_B, Ah, lda, (i + 2) * BK, tid);
            load_f16_tile(bregion + s * TILE_B, B, ldb, (i + 2) * BK, tid);
            CP_COMMIT();
        }
        int s = i % STAGES;
        compute_stage(sbase + s * TILE_B + Abase,
                      bregion + s * TILE_B + Bbase, acc);
        if (i + 2 < NITER) { CP_WAIT1(); } else { CP_WAIT0(); }
        __syncthreads();
    }
}

// ---------------- prepasses ----------------
__global__ __launch_bounds__(256) void cvt_inputs_kernel(const float* __restrict__ in) {
    const long n4 = (long)M_DIM * K1 / 4;
    for (long i = blockIdx.x * blockDim.x + threadIdx.x; i < n4;
         i += (long)gridDim.x * blockDim.x) {
        float4 v = ((const float4*)in)[i];
        uint2 o;
        o.x = pack_h2(v.x, v.y);
        o.y = pack_h2(v.z, v.w);
        ((uint2*)g_inH)[i] = o;
    }
}
__global__ __launch_bounds__(256) void wt_kernel(const float* __restrict__ w) {
    int i = blockIdx.x * blockDim.x + threadIdx.x;
    if (i < N_DIM * K1) {
        int n = i / K1, k = i % K1;
        g_WtH[i] = __float2half_rn(w[(long)k * N_DIM + n]);
    }
}

// ---------------- GEMM1: XtH = (inputs @ W)^T fp16 ----------------
__global__ __launch_bounds__(256, 1) void gemm1_kernel() {
    extern __shared__ char smem[];
    float acc[4][4][4];
    const int m0 = blockIdx.x * 128;

    gemm_mainloop<K1 / BK, false>(g_inH + (long)m0 * K1, K1, g_WtH, K1, acc, smem);

    const int wid = threadIdx.x >> 5, lid = threadIdx.x & 31;
    const int wr = wid >> 2, wc = wid & 3, gID = lid >> 2, tig = lid & 3;
    #pragma unroll
    for (int mt = 0; mt < 4; mt++)
        #pragma unroll
        for (int nt = 0; nt < 4; nt++) {
            int r = m0 + wr * 64 + mt * 16 + gID;
            int c = wc * 32 + nt * 8 + tig * 2;
            g_XtH[(long)c * M_DIM + r]           = __float2half_rn(acc[mt][nt][0]);
            g_XtH[(long)(c + 1) * M_DIM + r]     = __float2half_rn(acc[mt][nt][1]);
            g_XtH[(long)c * M_DIM + r + 8]       = __float2half_rn(acc[mt][nt][2]);
            g_XtH[(long)(c + 1) * M_DIM + r + 8] = __float2half_rn(acc[mt][nt][3]);
        }
}

// ---------------- GEMM2: out = adj @ X ----------------
__global__ __launch_bounds__(256, 1) void gemm2_kernel(const float* __restrict__ adj,
                                                       float* __restrict__ out) {
    extern __shared__ char smem[];
    float acc[4][4][4];
    const int m0 = blockIdx.x * 128;

    gemm_mainloop<M_DIM / BK, true>(adj + (long)m0 * M_DIM, M_DIM, g_XtH, M_DIM, acc, smem);

    const int wid = threadIdx.x >> 5, lid = threadIdx.x & 31;
    const int wr = wid >> 2, wc = wid & 3, gID = lid >> 2, tig = lid & 3;
    #pragma unroll
    for (int mt = 0; mt < 4; mt++)
        #pragma unroll
        for (int nt = 0; nt < 4; nt++) {
            long r = m0 + wr * 64 + mt * 16 + gID;
            int  c = wc * 32 + nt * 8 + tig * 2;
            *(float2*)&out[r * N_DIM + c]       = make_float2(acc[mt][nt][0], acc[mt][nt][1]);
            *(float2*)&out[(r + 8) * N_DIM + c] = make_float2(acc[mt][nt][2], acc[mt][nt][3]);
        }
}

// ---------------- launch ----------------
extern "C" void kernel_launch(void* const* d_in, const int* in_sizes, int n_in,
                              void* d_out, int out_size)
{
    const float* inputs  = (const float*)d_in[0];
    const float* adj     = (const float*)d_in[1];
    const float* weights = (const float*)d_in[2];
    float* out = (float*)d_out;

    cudaFuncSetAttribute(gemm1_kernel, cudaFuncAttributeMaxDynamicSharedMemorySize, SMEM_BYTES);
    cudaFuncSetAttribute(gemm2_kernel, cudaFuncAttributeMaxDynamicSharedMemorySize, SMEM_BYTES);

    cvt_inputs_kernel<<<1024, 256>>>(inputs);
    wt_kernel<<<(N_DIM * K1 + 255) / 256, 256>>>(weights);
    gemm1_kernel<<<M_DIM / 128, 256, SMEM_BYTES>>>();
    gemm2_kernel<<<M_DIM / 128, 256, SMEM_BYTES>>>(adj, out);
}

// round 8
// speedup vs baseline: 1.1738x; 1.0733x over previous
#include <cuda_runtime.h>
#include <cuda_fp16.h>
#include <cstdint>

// ---------------------------------------------------------------------------
// Shapes: inputs[16384,512] f32, adj[16384,16384] f32, W[512,128] f32
//   X   = inputs @ W   (2.1 GF)     out = adj @ X   (68.7 GF)
// Engine: mma.sync.aligned.m16n8k16.row.col.f32.f16.f16.f32.
// R8: L1 was the binding pipe (81.8%). 8 warps arranged (wr,wc,wk)=2x2x2:
// warp tile 64x64 over half of BK=64 -> A/B each ldmatrix'd 2x instead of
// 4x/2x: LDS 96->64KB per iter. wk-pairs reduce partials via SMEM once.
// ---------------------------------------------------------------------------

#define M_DIM 16384
#define N_DIM 128
#define K1    512

__device__ __align__(16) __half g_inH[(long)M_DIM * K1];   // inputs fp16 (16 MB)
__device__ __align__(16) __half g_WtH[N_DIM * K1];         // W^T fp16 [n][k]
__device__ __align__(16) __half g_XtH[(long)N_DIM * M_DIM];// X^T fp16 [n][m] (4 MB)

#define BK 64
#define STAGES 3
#define ROW_B 144                                 // 128 B data + 16 B pad
#define TILE_B (128 * ROW_B)                      // 18432 B per tile
#define SMEM_BYTES (STAGES * 2 * TILE_B)          // 110592 B

// ---------------- helpers ----------------
__device__ __forceinline__ uint32_t smem_u32(const void* p) {
    uint32_t a;
    asm("{ .reg .u64 t; cvta.to.shared.u64 t, %1; cvt.u32.u64 %0, t; }"
        : "=r"(a) : "l"(p));
    return a;
}
#define CP_ASYNC16(dst, src) \
    asm volatile("cp.async.cg.shared.global [%0], [%1], 16;" :: "r"(dst), "l"(src) : "memory")
#define CP_COMMIT()  asm volatile("cp.async.commit_group;" ::: "memory")
#define CP_WAIT1()   asm volatile("cp.async.wait_group 1;" ::: "memory")
#define CP_WAIT0()   asm volatile("cp.async.wait_group 0;" ::: "memory")

__device__ __forceinline__ void mma_f16(float c[4], const uint32_t a[4], const uint32_t b[2]) {
    asm volatile(
        "mma.sync.aligned.m16n8k16.row.col.f32.f16.f16.f32 "
        "{%0,%1,%2,%3}, {%4,%5,%6,%7}, {%8,%9}, {%0,%1,%2,%3};"
        : "+f"(c[0]), "+f"(c[1]), "+f"(c[2]), "+f"(c[3])
        : "r"(a[0]), "r"(a[1]), "r"(a[2]), "r"(a[3]), "r"(b[0]), "r"(b[1]));
}
__device__ __forceinline__ void ldsm4(uint32_t r[4], uint32_t addr) {
    asm volatile("ldmatrix.sync.aligned.m8n8.x4.shared.b16 {%0,%1,%2,%3}, [%4];"
                 : "=r"(r[0]), "=r"(r[1]), "=r"(r[2]), "=r"(r[3]) : "r"(addr));
}
__device__ __forceinline__ uint32_t pack_h2(float x, float y) {
    __half2 h = __float22half2_rn(make_float2(x, y));
    return *(uint32_t*)&h;
}

// ---------------- producers ----------------
// fp16 tile: 128 rows x 64 halves (128 B) -> 1024 cp.async over 256 threads.
__device__ __forceinline__ void load_f16_tile(
    uint32_t ts, const __half* __restrict__ T, long ldt, int k0, int tid)
{
    #pragma unroll
    for (int j = 0; j < 4; j++) {
        int idx = tid + j * 256;               // 0..1023
        int row = idx >> 3, c = idx & 7;
        CP_ASYNC16(ts + (uint32_t)(row * ROW_B + c * 16),
                   T + (long)row * ldt + k0 + c * 8);
    }
}
// f32 A tile (adj) -> registers: 128 rows x 64 f32, 32 f32/thread (contiguous 128B)
__device__ __forceinline__ void ldg_A(float4 rb[8], const float* __restrict__ A,
                                      long lda, int k0, int tid)
{
    const float* p = A + (long)(tid >> 1) * lda + k0 + (tid & 1) * 32;
    #pragma unroll
    for (int q = 0; q < 8; q++) rb[q] = *(const float4*)(p + q * 4);
}
// convert + STS 32 halves (64 B) at row*144 + half*64
__device__ __forceinline__ void sts_A_cvt(uint32_t as, const float4 rb[8], int tid)
{
    uint32_t off = as + (uint32_t)((tid >> 1) * ROW_B + (tid & 1) * 64);
    #pragma unroll
    for (int q = 0; q < 2; q++) {
        uint32_t p0 = pack_h2(rb[4*q+0].x, rb[4*q+0].y), p1 = pack_h2(rb[4*q+0].z, rb[4*q+0].w);
        uint32_t p2 = pack_h2(rb[4*q+1].x, rb[4*q+1].y), p3 = pack_h2(rb[4*q+1].z, rb[4*q+1].w);
        uint32_t p4 = pack_h2(rb[4*q+2].x, rb[4*q+2].y), p5 = pack_h2(rb[4*q+2].z, rb[4*q+2].w);
        uint32_t p6 = pack_h2(rb[4*q+3].x, rb[4*q+3].y), p7 = pack_h2(rb[4*q+3].z, rb[4*q+3].w);
        asm volatile("st.shared.v4.b32 [%0], {%1,%2,%3,%4};"
                     :: "r"(off + q*32), "r"(p0), "r"(p1), "r"(p2), "r"(p3) : "memory");
        asm volatile("st.shared.v4.b32 [%0], {%1,%2,%3,%4};"
                     :: "r"(off + q*32 + 16), "r"(p4), "r"(p5), "r"(p6), "r"(p7) : "memory");
    }
}

// ---------------- compute: warp 64x64 tile over its k32 half ----------------
// aA/aB already include the wk*64-byte k-offset.
__device__ __forceinline__ void compute_stage(uint32_t aA, uint32_t aB, float acc[4][8][4])
{
    #pragma unroll
    for (int kk = 0; kk < 2; kk++) {
        uint32_t a[4][4], b[4][4];
        #pragma unroll
        for (int mt = 0; mt < 4; mt++) ldsm4(a[mt], aA + mt * (16 * ROW_B) + kk * 32);
        #pragma unroll
        for (int p = 0; p < 4; p++)    ldsm4(b[p], aB + p * (16 * ROW_B) + kk * 32);
        #pragma unroll
        for (int mt = 0; mt < 4; mt++)
            #pragma unroll
            for (int nt = 0; nt < 8; nt++)
                mma_f16(acc[mt][nt], a[mt], &b[nt >> 1][(nt & 1) * 2]);
    }
}

// ---------------- main loop ----------------
template <int NITER, bool CONV>
__device__ __forceinline__ void gemm_mainloop(
    const void* __restrict__ Av, long lda,
    const __half* __restrict__ B, long ldb,
    float acc[4][8][4], char* smem)
{
    const int tid = threadIdx.x;
    const int wid = tid >> 5, lid = tid & 31;
    const int wk = wid >> 2;                  // k-half 0/1
    const int wr = (wid >> 1) & 1;            // row half
    const int wc = wid & 1;                   // col half
    const uint32_t sbase = smem_u32(smem);
    const uint32_t bregion = sbase + STAGES * TILE_B;

    const uint32_t Abase = (uint32_t)((wr * 64 + (lid & 15)) * ROW_B
                                      + ((lid >> 4) & 1) * 16 + wk * 64);
    const uint32_t Bbase = (uint32_t)((wc * 64 + ((lid >> 4) & 1) * 8 + (lid & 7)) * ROW_B
                                      + ((lid >> 3) & 1) * 16 + wk * 64);

    #pragma unroll
    for (int mt = 0; mt < 4; mt++)
        #pragma unroll
        for (int nt = 0; nt < 8; nt++)
            #pragma unroll
            for (int r = 0; r < 4; r++) acc[mt][nt][r] = 0.0f;

    const float*  Af = (const float*)Av;
    const __half* Ah = (const __half*)Av;
    float4 rb[8];

    if (CONV) ldg_A(rb, Af, lda, 0, tid);
    else      load_f16_tile(sbase, Ah, lda, 0, tid);
    load_f16_tile(bregion, B, ldb, 0, tid);
    CP_COMMIT();
    if (CONV) { sts_A_cvt(sbase, rb, tid); ldg_A(rb, Af, lda, BK, tid); }
    else      load_f16_tile(sbase + TILE_B, Ah, lda, BK, tid);
    load_f16_tile(bregion + TILE_B, B, ldb, BK, tid);
    CP_COMMIT();
    CP_WAIT1();
    __syncthreads();

    #pragma unroll 1
    for (int i = 0; i < NITER; i++) {
        if (CONV && (i + 1 < NITER))
            sts_A_cvt(sbase + ((i + 1) % STAGES) * TILE_B, rb, tid);
        if (i + 2 < NITER) {
            int s = (i + 2) % STAGES;
            if (CONV) ldg_A(rb, Af, lda, (i + 2) * BK, tid);
            else      load_f16_tile(sbase + s * TILE_B, Ah, lda, (i + 2) * BK, tid);
            load_f16_tile(bregion + s * TILE_B, B, ldb, (i + 2) * BK, tid);
            CP_COMMIT();
        }
        int s = i % STAGES;
        compute_stage(sbase + s * TILE_B + Abase,
                      bregion + s * TILE_B + Bbase, acc);
        if (i + 2 < NITER) { CP_WAIT1(); } else { CP_WAIT0(); }
        __syncthreads();
    }
}

// k-split reduction: wk=1 warps dump acc to SMEM; wk=0 warps add.
// Layout: pair (wr*2+wc) region of 32 lanes x 132 floats (pad vs conflicts).
__device__ __forceinline__ bool kreduce(float acc[4][8][4], char* smem)
{
    const int wid = threadIdx.x >> 5, lid = threadIdx.x & 31;
    const int wk = wid >> 2;
    const int pair = wid & 3;                  // (wr,wc)
    float* red = (float*)smem + pair * (32 * 132) + lid * 132;

    if (wk == 1) {
        #pragma unroll
        for (int mt = 0; mt < 4; mt++)
            #pragma unroll
            for (int nt = 0; nt < 8; nt++)
                #pragma unroll
                for (int r = 0; r < 4; r++)
                    red[mt * 32 + nt * 4 + r] = acc[mt][nt][r];
    }
    __syncthreads();
    if (wk == 0) {
        #pragma unroll
        for (int mt = 0; mt < 4; mt++)
            #pragma unroll
            for (int nt = 0; nt < 8; nt++)
                #pragma unroll
                for (int r = 0; r < 4; r++)
                    acc[mt][nt][r] += red[mt * 32 + nt * 4 + r];
    }
    return wk == 0;
}

// ---------------- prepasses ----------------
__global__ __launch_bounds__(256) void cvt_inputs_kernel(const float* __restrict__ in) {
    const long n4 = (long)M_DIM * K1 / 4;
    for (long i = blockIdx.x * blockDim.x + threadIdx.x; i < n4;
         i += (long)gridDim.x * blockDim.x) {
        float4 v = ((const float4*)in)[i];
        uint2 o;
        o.x = pack_h2(v.x, v.y);
        o.y = pack_h2(v.z, v.w);
        ((uint2*)g_inH)[i] = o;
    }
}
__global__ __launch_bounds__(256) void wt_kernel(const float* __restrict__ w) {
    int i = blockIdx.x * blockDim.x + threadIdx.x;
    if (i < N_DIM * K1) {
        int n = i / K1, k = i % K1;
        g_WtH[i] = __float2half_rn(w[(long)k * N_DIM + n]);
    }
}

// ---------------- GEMM1: XtH = (inputs @ W)^T fp16 ----------------
__global__ __launch_bounds__(256, 1) void gemm1_kernel() {
    extern __shared__ char smem[];
    float acc[4][8][4];
    const int m0 = blockIdx.x * 128;

    gemm_mainloop<K1 / BK, false>(g_inH + (long)m0 * K1, K1, g_WtH, K1, acc, smem);
    bool writer = kreduce(acc, smem);

    const int wid = threadIdx.x >> 5, lid = threadIdx.x & 31;
    const int wr = (wid >> 1) & 1, wc = wid & 1, gID = lid >> 2, tig = lid & 3;
    if (writer) {
        #pragma unroll
        for (int mt = 0; mt < 4; mt++)
            #pragma unroll
            for (int nt = 0; nt < 8; nt++) {
                int r = m0 + wr * 64 + mt * 16 + gID;
                int c = wc * 64 + nt * 8 + tig * 2;
                g_XtH[(long)c * M_DIM + r]           = __float2half_rn(acc[mt][nt][0]);
                g_XtH[(long)(c + 1) * M_DIM + r]     = __float2half_rn(acc[mt][nt][1]);
                g_XtH[(long)c * M_DIM + r + 8]       = __float2half_rn(acc[mt][nt][2]);
                g_XtH[(long)(c + 1) * M_DIM + r + 8] = __float2half_rn(acc[mt][nt][3]);
            }
    }
}

// ---------------- GEMM2: out = adj @ X ----------------
__global__ __launch_bounds__(256, 1) void gemm2_kernel(const float* __restrict__ adj,
                                                       float* __restrict__ out) {
    extern __shared__ char smem[];
    float acc[4][8][4];
    const int m0 = blockIdx.x * 128;

    gemm_mainloop<M_DIM / BK, true>(adj + (long)m0 * M_DIM, M_DIM, g_XtH, M_DIM, acc, smem);
    bool writer = kreduce(acc, smem);

    const int wid = threadIdx.x >> 5, lid = threadIdx.x & 31;
    const int wr = (wid >> 1) & 1, wc = wid & 1, gID = lid >> 2, tig = lid & 3;
    if (writer) {
        #pragma unroll
        for (int mt = 0; mt < 4; mt++)
            #pragma unroll
            for (int nt = 0; nt < 8; nt++) {
                long r = m0 + wr * 64 + mt * 16 + gID;
                int  c = wc * 64 + nt * 8 + tig * 2;
                *(float2*)&out[r * N_DIM + c]       = make_float2(acc[mt][nt][0], acc[mt][nt][1]);
                *(float2*)&out[(r + 8) * N_DIM + c] = make_float2(acc[mt][nt][2], acc[mt][nt][3]);
            }
    }
}

// ---------------- launch ----------------
extern "C" void kernel_launch(void* const* d_in, const int* in_sizes, int n_in,
                              void* d_out, int out_size)
{
    const float* inputs  = (const float*)d_in[0];
    const float* adj     = (const float*)d_in[1];
    const float* weights = (const float*)d_in[2];
    float* out = (float*)d_out;

    cudaFuncSetAttribute(gemm1_kernel, cudaFuncAttributeMaxDynamicSharedMemorySize, SMEM_BYTES);
    cudaFuncSetAttribute(gemm2_kernel, cudaFuncAttributeMaxDynamicSharedMemorySize, SMEM_BYTES);

    cvt_inputs_kernel<<<1024, 256>>>(inputs);
    wt_kernel<<<(N_DIM * K1 + 255) / 256, 256>>>(weights);
    gemm1_kernel<<<M_DIM / 128, 256, SMEM_BYTES>>>();
    gemm2_kernel<<<M_DIM / 128, 256, SMEM_BYTES>>>(adj, out);
}

// round 9
// speedup vs baseline: 1.3882x; 1.1827x over previous
#include <cuda_runtime.h>
#include <cuda_fp16.h>
#include <cstdint>

// ---------------------------------------------------------------------------
// Shapes: inputs[16384,512] f32, adj[16384,16384] f32, W[512,128] f32
//   X   = inputs @ W   (2.1 GF)     out = adj @ X   (68.7 GF)
// Engine: mma.sync.aligned.m16n8k16.row.col.f32.f16.f16.f32.
// R9: 512 threads / 16 warps (4x4), warp tile 32x32, acc 32 regs -> occ 25%
// (R8 was latency-exposed at 2 warps/SMSP). A-tile 32B chunks swizzled by
// (row>>3)&3 -> STS conflict-free; XOR folded into ldmatrix lane addresses.
// adj converted f32->fp16 inline (LDG->cvt->STS), reg-buffered 1 iter.
// ---------------------------------------------------------------------------

#define M_DIM 16384
#define N_DIM 128
#define K1    512

__device__ __align__(16) __half g_inH[(long)M_DIM * K1];   // inputs fp16 (16 MB)
__device__ __align__(16) __half g_WtH[N_DIM * K1];         // W^T fp16 [n][k]
__device__ __align__(16) __half g_XtH[(long)N_DIM * M_DIM];// X^T fp16 [n][m] (4 MB)

#define NTHREADS 512
#define BK 64
#define STAGES 3
#define ROW_B 144                                 // 128 B data + 16 B pad
#define TILE_B (128 * ROW_B)                      // 18432 B per tile
#define SMEM_BYTES (STAGES * 2 * TILE_B)          // 110592 B

// ---------------- helpers ----------------
__device__ __forceinline__ uint32_t smem_u32(const void* p) {
    uint32_t a;
    asm("{ .reg .u64 t; cvta.to.shared.u64 t, %1; cvt.u32.u64 %0, t; }"
        : "=r"(a) : "l"(p));
    return a;
}
#define CP_ASYNC16(dst, src) \
    asm volatile("cp.async.cg.shared.global [%0], [%1], 16;" :: "r"(dst), "l"(src) : "memory")
#define CP_COMMIT()  asm volatile("cp.async.commit_group;" ::: "memory")
#define CP_WAIT1()   asm volatile("cp.async.wait_group 1;" ::: "memory")
#define CP_WAIT0()   asm volatile("cp.async.wait_group 0;" ::: "memory")

__device__ __forceinline__ void mma_f16(float c[4], const uint32_t a[4], const uint32_t b[2]) {
    asm volatile(
        "mma.sync.aligned.m16n8k16.row.col.f32.f16.f16.f32 "
        "{%0,%1,%2,%3}, {%4,%5,%6,%7}, {%8,%9}, {%0,%1,%2,%3};"
        : "+f"(c[0]), "+f"(c[1]), "+f"(c[2]), "+f"(c[3])
        : "r"(a[0]), "r"(a[1]), "r"(a[2]), "r"(a[3]), "r"(b[0]), "r"(b[1]));
}
__device__ __forceinline__ void ldsm4(uint32_t r[4], uint32_t addr) {
    asm volatile("ldmatrix.sync.aligned.m8n8.x4.shared.b16 {%0,%1,%2,%3}, [%4];"
                 : "=r"(r[0]), "=r"(r[1]), "=r"(r[2]), "=r"(r[3]) : "r"(addr));
}
__device__ __forceinline__ uint32_t pack_h2(float x, float y) {
    __half2 h = __float22half2_rn(make_float2(x, y));
    return *(uint32_t*)&h;
}

// ---------------- producers ----------------
// B tile (always linear layout): 128 rows x 64 halves -> 1024 chunks / 512 thr.
__device__ __forceinline__ void load_B_tile(
    uint32_t ts, const __half* __restrict__ T, long ldt, int k0, int tid)
{
    #pragma unroll
    for (int j = 0; j < 2; j++) {
        int idx = tid + j * NTHREADS;          // 0..1023
        int row = idx >> 3, cc = idx & 7;
        CP_ASYNC16(ts + (uint32_t)(row * ROW_B + cc * 16),
                   T + (long)row * ldt + k0 + cc * 8);
    }
}
// A fp16 tile (gemm1), swizzled chunk layout.
__device__ __forceinline__ void load_A16_tile_sw(
    uint32_t ts, const __half* __restrict__ T, long ldt, int k0, int tid)
{
    #pragma unroll
    for (int j = 0; j < 2; j++) {
        int idx = tid + j * NTHREADS;
        int row = idx >> 3, cc = idx & 7;
        int s = (row >> 3) & 3;
        uint32_t dst = (uint32_t)(row * ROW_B + (((cc >> 1) ^ s) * 32) + (cc & 1) * 16);
        CP_ASYNC16(ts + dst, T + (long)row * ldt + k0 + cc * 8);
    }
}
// f32 A tile (adj) -> regs: 128 rows x 64 f32; 512 thr -> 16 f32/thread.
__device__ __forceinline__ void ldg_A(float4 rb[4], const float* __restrict__ A,
                                      long lda, int k0, int tid)
{
    const float* p = A + (long)(tid >> 2) * lda + k0 + (tid & 3) * 16;
    #pragma unroll
    for (int q = 0; q < 4; q++) rb[q] = *(const float4*)(p + q * 4);
}
// convert + STS 16 halves (32 B) at swizzled chunk position.
__device__ __forceinline__ void sts_A_cvt(uint32_t as, const float4 rb[4], int tid)
{
    int row = tid >> 2, c = tid & 3;
    int s = (row >> 3) & 3;
    uint32_t off = as + (uint32_t)(row * ROW_B + ((c ^ s) * 32));
    uint32_t p0 = pack_h2(rb[0].x, rb[0].y), p1 = pack_h2(rb[0].z, rb[0].w);
    uint32_t p2 = pack_h2(rb[1].x, rb[1].y), p3 = pack_h2(rb[1].z, rb[1].w);
    uint32_t p4 = pack_h2(rb[2].x, rb[2].y), p5 = pack_h2(rb[2].z, rb[2].w);
    uint32_t p6 = pack_h2(rb[3].x, rb[3].y), p7 = pack_h2(rb[3].z, rb[3].w);
    asm volatile("st.shared.v4.b32 [%0], {%1,%2,%3,%4};"
                 :: "r"(off), "r"(p0), "r"(p1), "r"(p2), "r"(p3) : "memory");
    asm volatile("st.shared.v4.b32 [%0], {%1,%2,%3,%4};"
                 :: "r"(off + 16), "r"(p4), "r"(p5), "r"(p6), "r"(p7) : "memory");
}

// ---------------- compute: warp 32x32 tile, BK=64 (4 k16 steps) -------------
// Aoff/sft: per-lane row terms (mt=0,1); Boff: per-lane B term.
__device__ __forceinline__ void compute_stage(
    uint32_t sA, uint32_t sB,
    uint32_t Aoff0, uint32_t Aoff1, uint32_t sft0, uint32_t sft1,
    uint32_t Boff, float acc[2][4][4])
{
    #pragma unroll
    for (int kk = 0; kk < 4; kk++) {
        uint32_t a[2][4], b[2][4];
        ldsm4(a[0], sA + Aoff0 + (((uint32_t)(kk << 5)) ^ sft0));
        ldsm4(a[1], sA + Aoff1 + (((uint32_t)(kk << 5)) ^ sft1));
        ldsm4(b[0], sB + Boff + kk * 32);
        ldsm4(b[1], sB + Boff + 16 * ROW_B + kk * 32);
        #pragma unroll
        for (int mt = 0; mt < 2; mt++)
            #pragma unroll
            for (int nt = 0; nt < 4; nt++)
                mma_f16(acc[mt][nt], a[mt], &b[nt >> 1][(nt & 1) * 2]);
    }
}

// ---------------- main loop ----------------
template <int NITER, bool CONV>
__device__ __forceinline__ void gemm_mainloop(
    const void* __restrict__ Av, long lda,
    const __half* __restrict__ B, long ldb,
    float acc[2][4][4], char* smem)
{
    const int tid = threadIdx.x;
    const int wid = tid >> 5, lid = tid & 31;
    const int wr = wid >> 2, wc = wid & 3;     // 4x4 warps
    const uint32_t sbase = smem_u32(smem);
    const uint32_t bregion = sbase + STAGES * TILE_B;

    // A lane terms (mt = 0,1): row = wr*32 + mt*16 + (lid&15)
    const int row0 = wr * 32 + (lid & 15);
    const int row1 = row0 + 16;
    const uint32_t sub16 = ((lid >> 4) & 1) * 16;
    const uint32_t Aoff0 = (uint32_t)(row0 * ROW_B) + sub16;
    const uint32_t Aoff1 = (uint32_t)(row1 * ROW_B) + sub16;
    const uint32_t sft0 = (uint32_t)(((row0 >> 3) & 3) << 5);
    const uint32_t sft1 = (uint32_t)(((row1 >> 3) & 3) << 5);
    // B lane term (validated mapping from R5/R7, warp n-extent 32)
    const uint32_t Boff = (uint32_t)((wc * 32 + ((lid >> 4) & 1) * 8 + (lid & 7)) * ROW_B
                                     + ((lid >> 3) & 1) * 16);

    #pragma unroll
    for (int mt = 0; mt < 2; mt++)
        #pragma unroll
        for (int nt = 0; nt < 4; nt++)
            #pragma unroll
            for (int r = 0; r < 4; r++) acc[mt][nt][r] = 0.0f;

    const float*  Af = (const float*)Av;
    const __half* Ah = (const __half*)Av;
    float4 rb[4];

    if (CONV) ldg_A(rb, Af, lda, 0, tid);
    else      load_A16_tile_sw(sbase, Ah, lda, 0, tid);
    load_B_tile(bregion, B, ldb, 0, tid);
    CP_COMMIT();
    if (CONV) { sts_A_cvt(sbase, rb, tid); ldg_A(rb, Af, lda, BK, tid); }
    else      load_A16_tile_sw(sbase + TILE_B, Ah, lda, BK, tid);
    load_B_tile(bregion + TILE_B, B, ldb, BK, tid);
    CP_COMMIT();
    CP_WAIT1();
    __syncthreads();

    #pragma unroll 1
    for (int i = 0; i < NITER; i++) {
        if (CONV && (i + 1 < NITER))
            sts_A_cvt(sbase + ((i + 1) % STAGES) * TILE_B, rb, tid);
        if (i + 2 < NITER) {
            int s = (i + 2) % STAGES;
            if (CONV) ldg_A(rb, Af, lda, (i + 2) * BK, tid);
            else      load_A16_tile_sw(sbase + s * TILE_B, Ah, lda, (i + 2) * BK, tid);
            load_B_tile(bregion + s * TILE_B, B, ldb, (i + 2) * BK, tid);
            CP_COMMIT();
        }
        int s = i % STAGES;
        compute_stage(sbase + s * TILE_B, bregion + s * TILE_B,
                      Aoff0, Aoff1, sft0, sft1, Boff, acc);
        if (i + 2 < NITER) { CP_WAIT1(); } else { CP_WAIT0(); }
        __syncthreads();
    }
}

// ---------------- prepasses ----------------
__global__ __launch_bounds__(256) void cvt_inputs_kernel(const float* __restrict__ in) {
    const long n4 = (long)M_DIM * K1 / 4;
    for (long i = blockIdx.x * blockDim.x + threadIdx.x; i < n4;
         i += (long)gridDim.x * blockDim.x) {
        float4 v = ((const float4*)in)[i];
        uint2 o;
        o.x = pack_h2(v.x, v.y);
        o.y = pack_h2(v.z, v.w);
        ((uint2*)g_inH)[i] = o;
    }
}
__global__ __launch_bounds__(256) void wt_kernel(const float* __restrict__ w) {
    int i = blockIdx.x * blockDim.x + threadIdx.x;
    if (i < N_DIM * K1) {
        int n = i / K1, k = i % K1;
        g_WtH[i] = __float2half_rn(w[(long)k * N_DIM + n]);
    }
}

// ---------------- GEMM1: XtH = (inputs @ W)^T fp16 ----------------
__global__ __launch_bounds__(NTHREADS, 1) void gemm1_kernel() {
    extern __shared__ char smem[];
    float acc[2][4][4];
    const int m0 = blockIdx.x * 128;

    gemm_mainloop<K1 / BK, false>(g_inH + (long)m0 * K1, K1, g_WtH, K1, acc, smem);

    const int wid = threadIdx.x >> 5, lid = threadIdx.x & 31;
    const int wr = wid >> 2, wc = wid & 3, gID = lid >> 2, tig = lid & 3;
    #pragma unroll
    for (int mt = 0; mt < 2; mt++)
        #pragma unroll
        for (int nt = 0; nt < 4; nt++) {
            int r = m0 + wr * 32 + mt * 16 + gID;
            int c = wc * 32 + nt * 8 + tig * 2;
            g_XtH[(long)c * M_DIM + r]           = __float2half_rn(acc[mt][nt][0]);
            g_XtH[(long)(c + 1) * M_DIM + r]     = __float2half_rn(acc[mt][nt][1]);
            g_XtH[(long)c * M_DIM + r + 8]       = __float2half_rn(acc[mt][nt][2]);
            g_XtH[(long)(c + 1) * M_DIM + r + 8] = __float2half_rn(acc[mt][nt][3]);
        }
}

// ---------------- GEMM2: out = adj @ X ----------------
__global__ __launch_bounds__(NTHREADS, 1) void gemm2_kernel(const float* __restrict__ adj,
                                                            float* __restrict__ out) {
    extern __shared__ char smem[];
    float acc[2][4][4];
    const int m0 = blockIdx.x * 128;

    gemm_mainloop<M_DIM / BK, true>(adj + (long)m0 * M_DIM, M_DIM, g_XtH, M_DIM, acc, smem);

    const int wid = threadIdx.x >> 5, lid = threadIdx.x & 31;
    const int wr = wid >> 2, wc = wid & 3, gID = lid >> 2, tig = lid & 3;
    #pragma unroll
    for (int mt = 0; mt < 2; mt++)
        #pragma unroll
        for (int nt = 0; nt < 4; nt++) {
            long r = m0 + wr * 32 + mt * 16 + gID;
            int  c = wc * 32 + nt * 8 + tig * 2;
            *(float2*)&out[r * N_DIM + c]       = make_float2(acc[mt][nt][0], acc[mt][nt][1]);
            *(float2*)&out[(r + 8) * N_DIM + c] = make_float2(acc[mt][nt][2], acc[mt][nt][3]);
        }
}

// ---------------- launch ----------------
extern "C" void kernel_launch(void* const* d_in, const int* in_sizes, int n_in,
                              void* d_out, int out_size)
{
    const float* inputs  = (const float*)d_in[0];
    const float* adj     = (const float*)d_in[1];
    const float* weights = (const float*)d_in[2];
    float* out = (float*)d_out;

    cudaFuncSetAttribute(gemm1_kernel, cudaFuncAttributeMaxDynamicSharedMemorySize, SMEM_BYTES);
    cudaFuncSetAttribute(gemm2_kernel, cudaFuncAttributeMaxDynamicSharedMemorySize, SMEM_BYTES);

    cvt_inputs_kernel<<<1024, 256>>>(inputs);
    wt_kernel<<<(N_DIM * K1 + 255) / 256, 256>>>(weights);
    gemm1_kernel<<<M_DIM / 128, NTHREADS, SMEM_BYTES>>>();
    gemm2_kernel<<<M_DIM / 128, NTHREADS, SMEM_BYTES>>>(adj, out);
}